// round 13
// baseline (speedup 1.0000x reference)
#include <cuda_runtime.h>
#include <cuda_bf16.h>
#include <cstdint>

#define Bb 4
#define Nn 512
#define Hh 8

// quantization constants
#define QE (127.0f / 7.0f)          // edge: clip +-7 sigma
#define QW (127.0f / 0.12f)         // we_w: clip +-0.12 (6 sigma at s=0.02)
#define KDQ ((7.0f / 127.0f) * (0.12f / 127.0f))

// ---------------- device scratch ----------------
__device__ float          g_preg[Bb * 128];
__device__ signed char    g_we8[128 * 128];                  // we_w^T [m][k] int8
__device__ signed char    g_edge8[(size_t)Bb * Nn * Nn * 128]; // edge pre-quantized int8
__device__ __nv_bfloat16  g_pre1bf[Bb * Nn * 128];           // pre1 (j-dependent) bf16
__device__ float          g_prerow[Bb * Nn * 128];           // pre2+pre_g+we_b (i-dependent)
__device__ float          g_val[Bb * Nn * 128];
__device__ float          g_skip[Bb * Nn * 128];
__device__ float          g_logits[(size_t)Bb * Hh * Nn * Nn]; // masked logits

// ---------------- helpers ----------------
__device__ __forceinline__ void mma_s8(int acc[4],
                                       unsigned a0, unsigned a1, unsigned a2, unsigned a3,
                                       unsigned b0, unsigned b1) {
    asm volatile(
        "mma.sync.aligned.m16n8k32.row.col.s32.s8.s8.s32 "
        "{%0,%1,%2,%3},{%4,%5,%6,%7},{%8,%9},{%0,%1,%2,%3};\n"
        : "+r"(acc[0]), "+r"(acc[1]), "+r"(acc[2]), "+r"(acc[3])
        : "r"(a0), "r"(a1), "r"(a2), "r"(a3), "r"(b0), "r"(b1));
}
__device__ __forceinline__ void ldsm_x4(unsigned& r0, unsigned& r1, unsigned& r2, unsigned& r3,
                                        unsigned addr) {
    asm volatile("ldmatrix.sync.aligned.m8n8.x4.shared.b16 {%0,%1,%2,%3}, [%4];\n"
                 : "=r"(r0), "=r"(r1), "=r"(r2), "=r"(r3) : "r"(addr));
}
__device__ __forceinline__ uint32_t smem_u32(const void* p) {
    uint32_t a;
    asm("{ .reg .u64 t; cvta.to.shared.u64 t, %1; cvt.u32.u64 %0, t; }" : "=r"(a) : "l"(p));
    return a;
}
__device__ __forceinline__ void cp16(uint32_t dst, const void* src) {
    asm volatile("cp.async.cg.shared.global [%0], [%1], 16;" :: "r"(dst), "l"(src));
}
#define CP_COMMIT() asm volatile("cp.async.commit_group;" ::: "memory")
#define CP_WAIT0()  asm volatile("cp.async.wait_group 0;" ::: "memory")
#define CP_WAIT1()  asm volatile("cp.async.wait_group 1;" ::: "memory")

__device__ __forceinline__ unsigned q4(float4 v) {
    int i0 = __float2int_rn(fminf(fmaxf(v.x * QE, -127.f), 127.f));
    int i1 = __float2int_rn(fminf(fmaxf(v.y * QE, -127.f), 127.f));
    int i2 = __float2int_rn(fminf(fmaxf(v.z * QE, -127.f), 127.f));
    int i3 = __float2int_rn(fminf(fmaxf(v.w * QE, -127.f), 127.f));
    return (unsigned)(i0 & 0xFF) | ((unsigned)(i1 & 0xFF) << 8)
         | ((unsigned)(i2 & 0xFF) << 16) | ((unsigned)i3 << 24);
}

// smem byte offsets for edge_k
#define OFF_SW8   0                  // [128][144] int8              18432
#define OFF_SE8   18432              // 2 x [64][144] int8           18432
#define OFF_SP    36864              // 2 x [64][136] bf16           34816
#define OFF_PRE   71680              // 128 f32
#define OFF_AW    72192              // 128 f32
#define OFF_AB    72704              // 8 f32
#define OFF_ADJ   72736              // 512 f32
#define EDGE_SMEM 74784

// ---------------- kernel 0: stream-quantize edge fp32 -> int8 ----------------
__global__ void __launch_bounds__(256) quant_k(const float* __restrict__ edge) {
    size_t base = (size_t)blockIdx.x * 1024 + threadIdx.x;
    const float4* e4 = (const float4*)edge;
    unsigned* o4 = (unsigned*)g_edge8;
    #pragma unroll
    for (int it = 0; it < 4; it++) {
        size_t idx = base + (size_t)it * 256;
        o4[idx] = q4(e4[idx]);
    }
}

// ---------------- kernel 1: pre_g + we_w^T int8 ----------------
__global__ void prep_k(const float* __restrict__ graph, const float* __restrict__ wg_w,
                       const float* __restrict__ wg_b, const float* __restrict__ we_w) {
    int blk = blockIdx.x;
    int t = threadIdx.x;
    if (blk < 4) {
        float s = wg_b[t];
        #pragma unroll 4
        for (int k = 0; k < 128; k++)
            s = fmaf(graph[blk * 128 + k], wg_w[k * 128 + t], s);
        g_preg[blk * 128 + t] = s;
    } else {
        int base = (blk - 4) * 4096;
        #pragma unroll
        for (int it = 0; it < 32; it++) {
            int idx = base + t + it * 128;
            int k = idx >> 7, m = idx & 127;
            int q = __float2int_rn(fminf(fmaxf(we_w[idx] * QW, -127.f), 127.f));
            g_we8[m * 128 + k] = (signed char)q;
        }
    }
}

// ---------------- kernel 2: node precompute ----------------
__global__ void node_k(const float* __restrict__ node,
                       const float* __restrict__ m_w, const float* __restrict__ m_b,
                       const float* __restrict__ skip_w, const float* __restrict__ skip_b,
                       const float* __restrict__ w1_w, const float* __restrict__ w1_b,
                       const float* __restrict__ w2_w, const float* __restrict__ w2_b,
                       const float* __restrict__ we_b) {
    __shared__ float sn[8][128];
    int blk = blockIdx.x;
    int b = blk >> 6;
    int n0 = (blk & 63) * 8;
    int t = threadIdx.x;

    float4* snv = (float4*)sn;
    const float4* gn = (const float4*)(node + ((size_t)(b * 512) + n0) * 128);
    snv[t] = gn[t];
    snv[t + 128] = gn[t + 128];
    __syncthreads();

    int o = t;
    float av[8], as_[8], a1[8], a2[8];
    #pragma unroll
    for (int nn = 0; nn < 8; nn++) { av[nn] = 0.f; as_[nn] = 0.f; a1[nn] = 0.f; a2[nn] = 0.f; }

    for (int k = 0; k < 128; k++) {
        float wm = m_w[k * 128 + o];
        float ws = skip_w[k * 128 + o];
        float w1 = w1_w[k * 128 + o];
        float w2 = w2_w[k * 128 + o];
        #pragma unroll
        for (int nn = 0; nn < 8; nn++) {
            float x = sn[nn][k];
            av[nn]  = fmaf(x, wm, av[nn]);
            as_[nn] = fmaf(x, ws, as_[nn]);
            a1[nn]  = fmaf(x, w1, a1[nn]);
            a2[nn]  = fmaf(x, w2, a2[nn]);
        }
    }
    float addc = g_preg[b * 128 + o] + we_b[o];
    #pragma unroll
    for (int nn = 0; nn < 8; nn++) {
        size_t base = ((size_t)(b * 512) + n0 + nn) * 128 + o;
        g_val[base]    = av[nn] + m_b[o];
        g_skip[base]   = as_[nn] + skip_b[o];
        g_pre1bf[base] = __float2bfloat16(a1[nn] + w1_b[o]);
        g_prerow[base] = a2[nn] + w2_b[o] + addc;
    }
}

// ---------------- kernel 3: edge GEMM (int8 IMMA, cp.async double-buffered) ----------
// block = (b, i); 256 threads = 8 warps; warp w: j-block (w&3)*16, m-block (w>>2)*64.
__global__ void __launch_bounds__(256, 3) edge_k(const float* __restrict__ adj,
                                                 const float* __restrict__ a_w,
                                                 const float* __restrict__ a_b) {
    extern __shared__ char sm[];
    uint32_t smb = smem_u32(sm);
    char* sW8 = sm + OFF_SW8;
    __nv_bfloat16* sPbase = (__nv_bfloat16*)(sm + OFF_SP);
    float* sPre = (float*)(sm + OFF_PRE);
    float* sAw  = (float*)(sm + OFF_AW);
    float* sAb  = (float*)(sm + OFF_AB);
    float* sAdj = (float*)(sm + OFF_ADJ);

    int blk = blockIdx.x;
    int b = blk >> 9;
    int i = blk & 511;
    int t = threadIdx.x;
    int w = t >> 5;
    int lane = t & 31;

    { // stage we8: 16384 B = 1024 uint4
        const uint4* gw = (const uint4*)g_we8;
        #pragma unroll
        for (int it = 0; it < 4; it++) {
            int idx = t + it * 256;
            int r = idx >> 3, c = idx & 7;
            *(uint4*)(sW8 + r * 144 + c * 16) = gw[idx];
        }
    }
    if (t < 128) {
        sPre[t] = g_prerow[((size_t)(b * 512) + i) * 128 + t];
        sAw[t] = a_w[t];
        ((float4*)sAdj)[t] = ((const float4*)(adj + ((size_t)(b * 512) + i) * 512))[t];
    }
    if (t < 8) sAb[t] = a_b[t];

    const char* eBase = (const char*)g_edge8 + ((size_t)(b * 512 + i)) * 512 * 128;
    const char* pBase = (const char*)(g_pre1bf + ((size_t)(b * 512)) * 128);

    // issue tile `tile` into buffer `bf`
    auto issue = [&](int tile, int bf) {
        const char* ge = eBase + (size_t)tile * 8192;      // 64 rows * 128 B
        uint32_t seDst = smb + OFF_SE8 + bf * 9216;
        #pragma unroll
        for (int it = 0; it < 2; it++) {
            int idx = t + it * 256;                        // 0..511
            int r = idx >> 3, c = idx & 7;
            cp16(seDst + r * 144 + c * 16, ge + idx * 16);
        }
        const char* gp = pBase + (size_t)tile * 16384;     // 64 rows * 256 B
        uint32_t spDst = smb + OFF_SP + bf * 17408;
        #pragma unroll
        for (int it = 0; it < 4; it++) {
            int idx = t + it * 256;                        // 0..1023
            int r = idx >> 4, c = idx & 15;
            cp16(spDst + r * 272 + c * 16, gp + idx * 16);
        }
    };

    issue(0, 0);
    CP_COMMIT();

    int jb = (w & 3) << 4;
    int mb = (w >> 2) << 6;
    int qr = lane >> 2;
    int qc = (lane & 3) << 1;
    int h0 = mb >> 4;

    // ldmatrix lane addressing (16-byte column units, pitch 144)
    int row_a = jb + (lane & 15);
    unsigned aB0 = smem_u32(sm + OFF_SE8) + row_a * 144 + (((lane >> 4) & 1) << 4);
    unsigned aB1 = aB0 + 9216;
    unsigned bBase[4];
    #pragma unroll
    for (int p = 0; p < 4; p++) {
        int row_b = mb + p * 16 + ((lane >> 4) & 1) * 8 + (lane & 7);
        bBase[p] = (unsigned)__cvta_generic_to_shared(
            sW8 + row_b * 144 + (((lane >> 3) & 1) << 4));
    }

    for (int tt = 0; tt < 8; tt++) {
        int buf = tt & 1;
        if (tt < 7) { issue(tt + 1, buf ^ 1); CP_COMMIT(); }
        if (tt < 7) CP_WAIT1(); else CP_WAIT0();
        __syncthreads();

        int acc[8][4];
        #pragma unroll
        for (int nt = 0; nt < 8; nt++)
            #pragma unroll
            for (int q = 0; q < 4; q++) acc[nt][q] = 0;

        unsigned aAddr = buf ? aB1 : aB0;
        #pragma unroll
        for (int ks = 0; ks < 4; ks++) {          // k32 per step, K=128
            unsigned a0, a1, a2, a3;
            ldsm_x4(a0, a1, a2, a3, aAddr + ks * 32);
            #pragma unroll
            for (int p = 0; p < 4; p++) {
                unsigned b0, b1, b2, b3;
                ldsm_x4(b0, b1, b2, b3, bBase[p] + ks * 32);
                mma_s8(acc[2 * p],     a0, a1, a2, a3, b0, b1);
                mma_s8(acc[2 * p + 1], a0, a1, a2, a3, b2, b3);
            }
        }

        // epilogue: dequant + prerow(i) + pre1(j), leaky_relu, a_w, +mask bias
        int j0 = tt * 64;
        const __nv_bfloat16* sPb = sPbase + buf * 8704;    // 17408 B / 2
        #pragma unroll
        for (int hh = 0; hh < 4; hh++) {
            int h = h0 + hh;
            #pragma unroll
            for (int q2 = 0; q2 < 2; q2++) {
                int row = jb + qr + (q2 << 3);
                float s = 0.f;
                #pragma unroll
                for (int np = 0; np < 2; np++) {
                    int nt = hh * 2 + np;
                    #pragma unroll
                    for (int c0 = 0; c0 < 2; c0++) {
                        int m = mb + nt * 8 + qc + c0;
                        float p = (float)acc[nt][q2 * 2 + c0] * KDQ + sPre[m]
                                + __bfloat162float(sPb[row * 136 + m]);
                        p = (p > 0.f) ? p : 0.01f * p;
                        s = fmaf(p, sAw[m], s);
                    }
                }
                s += __shfl_xor_sync(0xffffffffu, s, 1);
                s += __shfl_xor_sync(0xffffffffu, s, 2);
                if ((lane & 3) == 0) {
                    float bias = (sAdj[j0 + row] - 1.0f) * 1e9f;
                    g_logits[((size_t)((b * 8 + h) * 512 + i)) * 512 + j0 + row] =
                        s + sAb[h] + bias;
                }
            }
        }
        __syncthreads();
    }
}

// ---------------- kernel 4: fused softmax + coefs@values + skip + relu + LN ----------
// block = (b, 2 i's), 512 threads = 16 warps.
__global__ void __launch_bounds__(512) out_k(const float* __restrict__ ln_scale,
                                             const float* __restrict__ ln_offset,
                                             float* __restrict__ out) {
    __shared__ float sc[2][8][512];      // 32 KB (logits -> coefs in place)
    __shared__ float sacc[4][2][128];    // 4 KB
    __shared__ float red[2][4][2];
    int blk = blockIdx.x;
    int b = blk >> 8;                    // 0..3
    int i0 = (blk & 255) * 2;            // 0..510
    int t = threadIdx.x;
    int w = t >> 5;
    int lane = t & 31;

    { // stage masked logits for 2 i's x 8 heads x 512 j  (2048 float4)
        float4* scv = (float4*)sc;
        const float4* gl = (const float4*)g_logits;
        #pragma unroll
        for (int it = 0; it < 4; it++) {
            int q = t + it * 512;               // 0..2047
            int ii = q >> 10;
            int h = (q >> 7) & 7;
            int c = q & 127;
            scv[q] = gl[((size_t)((b * 8 + h) * 512) + i0 + ii) * 128 + c];
        }
    }
    __syncthreads();

    { // softmax: warp w handles row (ii = w>>3, h = w&7)
        float* row = sc[w >> 3][w & 7];
        float x[16];
        #pragma unroll
        for (int k = 0; k < 16; k++) x[k] = row[lane + k * 32];
        float m = x[0];
        #pragma unroll
        for (int k = 1; k < 16; k++) m = fmaxf(m, x[k]);
        #pragma unroll
        for (int off = 16; off > 0; off >>= 1)
            m = fmaxf(m, __shfl_xor_sync(0xffffffffu, m, off));
        float e[16], s = 0.f;
        #pragma unroll
        for (int k = 0; k < 16; k++) { e[k] = __expf(x[k] - m); s += e[k]; }
        #pragma unroll
        for (int off = 16; off > 0; off >>= 1)
            s += __shfl_xor_sync(0xffffffffu, s, off);
        float inv = 1.0f / s;
        #pragma unroll
        for (int k = 0; k < 16; k++) row[lane + k * 32] = e[k] * inv;
    }
    __syncthreads();

    {
        int o = t & 127;
        int jq = t >> 7;                        // 0..3 j-quarter
        int h = o >> 4;
        const float* vb = g_val + (size_t)b * 65536 + (size_t)(jq * 128) * 128 + o;
        const float* cf0 = &sc[0][h][jq * 128];
        const float* cf1 = &sc[1][h][jq * 128];
        float a0 = 0.f, a1 = 0.f;
        #pragma unroll 8
        for (int j = 0; j < 128; j++) {
            float v = vb[(size_t)j * 128];
            a0 = fmaf(cf0[j], v, a0);
            a1 = fmaf(cf1[j], v, a1);
        }
        sacc[jq][0][o] = a0;
        sacc[jq][1][o] = a1;
    }
    __syncthreads();

    int o2 = t & 127;
    int i2 = (t >> 7) & 1;
    bool active = t < 256;
    float r = 0.f;
    size_t base = ((size_t)(b * 512) + i0 + i2) * 128 + o2;
    if (active) {
        r = sacc[0][i2][o2] + sacc[1][i2][o2] + sacc[2][i2][o2] + sacc[3][i2][o2]
          + g_skip[base];
        r = fmaxf(r, 0.f);
        float s1 = r, s2 = r * r;
        #pragma unroll
        for (int off = 16; off > 0; off >>= 1) {
            s1 += __shfl_xor_sync(0xffffffffu, s1, off);
            s2 += __shfl_xor_sync(0xffffffffu, s2, off);
        }
        if (lane == 0) {
            int wq = (t >> 5) & 3;
            red[i2][wq][0] = s1;
            red[i2][wq][1] = s2;
        }
    }
    __syncthreads();
    if (active) {
        float s1 = red[i2][0][0] + red[i2][1][0] + red[i2][2][0] + red[i2][3][0];
        float s2 = red[i2][0][1] + red[i2][1][1] + red[i2][2][1] + red[i2][3][1];
        float mean = s1 * (1.0f / 128.0f);
        float var = s2 * (1.0f / 128.0f) - mean * mean;
        out[base] = (r - mean) * rsqrtf(var + 1e-5f) * ln_scale[o2] + ln_offset[o2];
    }
}

// ---------------- launch ----------------
extern "C" void kernel_launch(void* const* d_in, const int* in_sizes, int n_in,
                              void* d_out, int out_size) {
    const float* node   = (const float*)d_in[0];
    const float* edge   = (const float*)d_in[1];
    const float* graph  = (const float*)d_in[2];
    const float* adj    = (const float*)d_in[3];
    const float* m_w    = (const float*)d_in[5];
    const float* m_b    = (const float*)d_in[6];
    const float* skip_w = (const float*)d_in[7];
    const float* skip_b = (const float*)d_in[8];
    const float* w1_w   = (const float*)d_in[9];
    const float* w1_b   = (const float*)d_in[10];
    const float* w2_w   = (const float*)d_in[11];
    const float* w2_b   = (const float*)d_in[12];
    const float* we_w   = (const float*)d_in[13];
    const float* we_b   = (const float*)d_in[14];
    const float* wg_w   = (const float*)d_in[15];
    const float* wg_b   = (const float*)d_in[16];
    const float* a_w    = (const float*)d_in[17];
    const float* a_b    = (const float*)d_in[18];
    const float* ln_s   = (const float*)d_in[19];
    const float* ln_o   = (const float*)d_in[20];
    float* out = (float*)d_out;

    cudaFuncSetAttribute(edge_k, cudaFuncAttributeMaxDynamicSharedMemorySize, EDGE_SMEM);

    quant_k<<<32768, 256>>>(edge);
    prep_k<<<8, 128>>>(graph, wg_w, wg_b, we_w);
    node_k<<<256, 128>>>(node, m_w, m_b, skip_w, skip_b, w1_w, w1_b, w2_w, w2_b, we_b);
    edge_k<<<2048, 256, EDGE_SMEM>>>(adj, a_w, a_b);
    out_k<<<1024, 512>>>(ln_s, ln_o, out);
}

// round 15
// speedup vs baseline: 1.5335x; 1.5335x over previous
#include <cuda_runtime.h>
#include <cuda_bf16.h>
#include <cstdint>

#define Bb 4
#define Nn 512
#define Hh 8

// ---------------- device scratch ----------------
__device__ float          g_preg[Bb * 128];
__device__ __nv_bfloat16  g_wetbf[128 * 128];                // we_w^T [m][k] bf16
__device__ __nv_bfloat16  g_pre1bf[Bb * Nn * 128];           // pre1 (j-dependent) bf16
__device__ float          g_prerow[Bb * Nn * 128];           // pre2+pre_g+we_b (i-dependent)
__device__ float          g_val[Bb * Nn * 128];
__device__ float          g_skip[Bb * Nn * 128];
__device__ float          g_logits[(size_t)Bb * Hh * Nn * Nn]; // masked logits

// ---------------- helpers ----------------
__device__ __forceinline__ void mma_bf16(float acc[4],
                                         unsigned a0, unsigned a1, unsigned a2, unsigned a3,
                                         unsigned b0, unsigned b1) {
    asm volatile(
        "mma.sync.aligned.m16n8k16.row.col.f32.bf16.bf16.f32 "
        "{%0,%1,%2,%3},{%4,%5,%6,%7},{%8,%9},{%0,%1,%2,%3};\n"
        : "+f"(acc[0]), "+f"(acc[1]), "+f"(acc[2]), "+f"(acc[3])
        : "r"(a0), "r"(a1), "r"(a2), "r"(a3), "r"(b0), "r"(b1));
}
__device__ __forceinline__ void ldsm_x4(unsigned& r0, unsigned& r1, unsigned& r2, unsigned& r3,
                                        unsigned addr) {
    asm volatile("ldmatrix.sync.aligned.m8n8.x4.shared.b16 {%0,%1,%2,%3}, [%4];\n"
                 : "=r"(r0), "=r"(r1), "=r"(r2), "=r"(r3) : "r"(addr));
}

// ---------------- kernel 0: fill logits with -3e38 (unselected rows) ----------------
// g_logits = 4*8*512*512 floats = 2,097,152 float4; 2048 blocks x 1024 float4 each.
__global__ void __launch_bounds__(256) fill_k() {
    float4* p = (float4*)g_logits;
    size_t base = (size_t)blockIdx.x * 1024 + threadIdx.x;
    float4 v = make_float4(-3e38f, -3e38f, -3e38f, -3e38f);
    #pragma unroll
    for (int it = 0; it < 4; it++) p[base + (size_t)it * 256] = v;
}

// ---------------- kernel 1: pre_g + we_w^T bf16 ----------------
__global__ void prep_k(const float* __restrict__ graph, const float* __restrict__ wg_w,
                       const float* __restrict__ wg_b, const float* __restrict__ we_w) {
    int blk = blockIdx.x;
    int t = threadIdx.x;
    if (blk < 4) {
        float s = wg_b[t];
        #pragma unroll 4
        for (int k = 0; k < 128; k++)
            s = fmaf(graph[blk * 128 + k], wg_w[k * 128 + t], s);
        g_preg[blk * 128 + t] = s;
    } else {
        int base = (blk - 4) * 4096;
        #pragma unroll
        for (int it = 0; it < 32; it++) {
            int idx = base + t + it * 128;
            int k = idx >> 7, m = idx & 127;
            g_wetbf[m * 128 + k] = __float2bfloat16(we_w[idx]);
        }
    }
}

// ---------------- kernel 2: node precompute ----------------
__global__ void node_k(const float* __restrict__ node,
                       const float* __restrict__ m_w, const float* __restrict__ m_b,
                       const float* __restrict__ skip_w, const float* __restrict__ skip_b,
                       const float* __restrict__ w1_w, const float* __restrict__ w1_b,
                       const float* __restrict__ w2_w, const float* __restrict__ w2_b,
                       const float* __restrict__ we_b) {
    __shared__ float sn[8][128];
    int blk = blockIdx.x;
    int b = blk >> 6;
    int n0 = (blk & 63) * 8;
    int t = threadIdx.x;

    float4* snv = (float4*)sn;
    const float4* gn = (const float4*)(node + ((size_t)(b * 512) + n0) * 128);
    snv[t] = gn[t];
    snv[t + 128] = gn[t + 128];
    __syncthreads();

    int o = t;
    float av[8], as_[8], a1[8], a2[8];
    #pragma unroll
    for (int nn = 0; nn < 8; nn++) { av[nn] = 0.f; as_[nn] = 0.f; a1[nn] = 0.f; a2[nn] = 0.f; }

    for (int k = 0; k < 128; k++) {
        float wm = m_w[k * 128 + o];
        float ws = skip_w[k * 128 + o];
        float w1 = w1_w[k * 128 + o];
        float w2 = w2_w[k * 128 + o];
        #pragma unroll
        for (int nn = 0; nn < 8; nn++) {
            float x = sn[nn][k];
            av[nn]  = fmaf(x, wm, av[nn]);
            as_[nn] = fmaf(x, ws, as_[nn]);
            a1[nn]  = fmaf(x, w1, a1[nn]);
            a2[nn]  = fmaf(x, w2, a2[nn]);
        }
    }
    float addc = g_preg[b * 128 + o] + we_b[o];
    #pragma unroll
    for (int nn = 0; nn < 8; nn++) {
        size_t base = ((size_t)(b * 512) + n0 + nn) * 128 + o;
        g_val[base]    = av[nn] + m_b[o];
        g_skip[base]   = as_[nn] + skip_b[o];
        g_pre1bf[base] = __float2bfloat16(a1[nn] + w1_b[o]);
        g_prerow[base] = a2[nn] + w2_b[o] + addc;
    }
}

// ---------------- kernel 3: masked-compacted edge GEMM (bf16 mma) ----------------
// block = (b, i); 256 threads = 8 warps. Only unmasked j rows (adj=1) are gathered
// and processed: ceil(cnt/64) tiles instead of 8.
__global__ void __launch_bounds__(256, 3) edge_k(const float* __restrict__ edge,
                                                 const float* __restrict__ adj,
                                                 const float* __restrict__ a_w,
                                                 const float* __restrict__ a_b) {
    extern __shared__ char smraw[];
    __nv_bfloat16* sW = (__nv_bfloat16*)smraw;    // [128][136]  34816 B
    __nv_bfloat16* sE = sW + 128 * 136;           // [64][136]   17408 B
    __nv_bfloat16* sP = sE + 64 * 136;            // [64][136]   17408 B
    float* sPre = (float*)(sP + 64 * 136);        // [128]
    float* sAw  = sPre + 128;                     // [128]
    float* sAb  = sAw + 128;                      // [8]
    __shared__ unsigned short sIdx[512];
    __shared__ int sWsum[8];

    int blk = blockIdx.x;
    int b = blk >> 9;
    int i = blk & 511;
    int t = threadIdx.x;
    int w = t >> 5;
    int lane = t & 31;

    { // stage we_w^T : 2048 uint4
        const uint4* gw = (const uint4*)g_wetbf;
        #pragma unroll
        for (int it = 0; it < 8; it++) {
            int idx = t + it * 256;
            int r = idx >> 4, c = idx & 15;
            *(uint4*)(sW + r * 136 + c * 8) = gw[idx];
        }
    }
    if (t < 128) {
        sPre[t] = g_prerow[((size_t)(b * 512) + i) * 128 + t];
        sAw[t] = a_w[t];
    }
    if (t < 8) sAb[t] = a_b[t];

    // ---- compact unmasked j indices (adj row = exactly 0.0 / 1.0) ----
    const float2 arow = *(const float2*)(adj + ((size_t)(b * 512) + i) * 512 + 2 * t);
    int c0 = arow.x > 0.5f;
    int c1 = arow.y > 0.5f;
    int c = c0 + c1;
    int incl = c;
    #pragma unroll
    for (int off = 1; off < 32; off <<= 1) {
        int v = __shfl_up_sync(0xffffffffu, incl, off);
        if (lane >= off) incl += v;
    }
    if (lane == 31) sWsum[w] = incl;
    __syncthreads();
    int base = 0, total = 0;
    #pragma unroll
    for (int k = 0; k < 8; k++) {
        int sv = sWsum[k];
        if (k < w) base += sv;
        total += sv;
    }
    int excl = base + incl - c;
    if (c0) sIdx[excl] = (unsigned short)(2 * t);
    if (c1) sIdx[excl + c0] = (unsigned short)(2 * t + 1);
    int nt = (total + 63) >> 6;
    for (int r = total + t; r < (nt << 6); r += 256) sIdx[r] = 0;  // pad with valid row
    __syncthreads();

    int jb = (w & 3) << 4;
    int mb = (w >> 2) << 6;
    int qr = lane >> 2;
    int qc = (lane & 3) << 1;
    int h0 = mb >> 4;

    // ldmatrix lane addressing
    int row_a = jb + (lane & 7) + (((lane >> 3) & 1) << 3);
    int colc_a = ((lane >> 4) & 1) << 3;
    unsigned aBase = (unsigned)__cvta_generic_to_shared(sE + row_a * 136 + colc_a);
    unsigned bBase[4];
    #pragma unroll
    for (int p = 0; p < 4; p++) {
        int row_b = mb + (((p << 1) + (lane >> 4)) << 3) + (lane & 7);
        bBase[p] = (unsigned)__cvta_generic_to_shared(sW + row_b * 136 + (((lane >> 3) & 1) << 3));
    }

    const float4* eB = (const float4*)(edge + (((size_t)(b * 512 + i)) * 512) * 128);
    const uint4*  pB = (const uint4*)(g_pre1bf + ((size_t)(b * 512)) * 128);

    for (int tt = 0; tt < nt; tt++) {
        __syncthreads();
        // gather selected edge rows -> bf16 smem
        #pragma unroll
        for (int it = 0; it < 8; it++) {
            int idx = t + it * 256;            // 0..2047 float4 slots (64 rows x 32)
            int slot = idx >> 5, cc = idx & 31;
            int j = sIdx[(tt << 6) + slot];
            float4 v = eB[(size_t)j * 32 + cc];
            __nv_bfloat162 p0 = __floats2bfloat162_rn(v.x, v.y);
            __nv_bfloat162 p1 = __floats2bfloat162_rn(v.z, v.w);
            uint2 u;
            u.x = *(unsigned*)&p0;
            u.y = *(unsigned*)&p1;
            *(uint2*)(sE + slot * 136 + cc * 4) = u;
        }
        // gather selected pre1 rows (bf16): 64 rows x 16 uint4
        #pragma unroll
        for (int it = 0; it < 4; it++) {
            int idx = t + it * 256;            // 0..1023
            int slot = idx >> 4, cc = idx & 15;
            int j = sIdx[(tt << 6) + slot];
            *(uint4*)(sP + slot * 136 + cc * 8) = pB[(size_t)j * 16 + cc];
        }
        __syncthreads();

        float acc[8][4];
        #pragma unroll
        for (int ntl = 0; ntl < 8; ntl++)
            #pragma unroll
            for (int q = 0; q < 4; q++) acc[ntl][q] = 0.f;

        #pragma unroll
        for (int ks = 0; ks < 8; ks++) {
            unsigned a0, a1, a2, a3;
            ldsm_x4(a0, a1, a2, a3, aBase + ks * 32);
            #pragma unroll
            for (int p = 0; p < 4; p++) {
                unsigned b0, b1, b2, b3;
                ldsm_x4(b0, b1, b2, b3, bBase[p] + ks * 32);
                mma_bf16(acc[2 * p],     a0, a1, a2, a3, b0, b1);
                mma_bf16(acc[2 * p + 1], a0, a1, a2, a3, b2, b3);
            }
        }

        // epilogue: + prerow(i) + pre1(j), leaky_relu, a_w; store to gathered j
        #pragma unroll
        for (int hh = 0; hh < 4; hh++) {
            int h = h0 + hh;
            #pragma unroll
            for (int q2 = 0; q2 < 2; q2++) {
                int row = jb + qr + (q2 << 3);
                float s = 0.f;
                #pragma unroll
                for (int np = 0; np < 2; np++) {
                    int ntl = hh * 2 + np;
                    #pragma unroll
                    for (int cz = 0; cz < 2; cz++) {
                        int m = mb + ntl * 8 + qc + cz;
                        float p = acc[ntl][q2 * 2 + cz] + sPre[m]
                                + __bfloat162float(sP[row * 136 + m]);
                        p = (p > 0.f) ? p : 0.01f * p;
                        s = fmaf(p, sAw[m], s);
                    }
                }
                s += __shfl_xor_sync(0xffffffffu, s, 1);
                s += __shfl_xor_sync(0xffffffffu, s, 2);
                int gslot = (tt << 6) + row;
                if ((lane & 3) == 0 && gslot < total) {
                    int j = sIdx[gslot];
                    // adj==1 for selected rows -> mask bias is 0
                    g_logits[((size_t)((b * 8 + h) * 512 + i)) * 512 + j] = s + sAb[h];
                }
            }
        }
    }
}

// ---------------- kernel 4: fused softmax + coefs@values + skip + relu + LN ----------
// block = (b, 2 i's), 512 threads = 16 warps.
__global__ void __launch_bounds__(512) out_k(const float* __restrict__ ln_scale,
                                             const float* __restrict__ ln_offset,
                                             float* __restrict__ out) {
    __shared__ float sc[2][8][512];      // 32 KB (logits -> coefs in place)
    __shared__ float sacc[4][2][128];    // 4 KB
    __shared__ float red[2][4][2];
    int blk = blockIdx.x;
    int b = blk >> 8;                    // 0..3
    int i0 = (blk & 255) * 2;            // 0..510
    int t = threadIdx.x;
    int w = t >> 5;
    int lane = t & 31;

    { // stage masked logits for 2 i's x 8 heads x 512 j  (2048 float4)
        float4* scv = (float4*)sc;
        const float4* gl = (const float4*)g_logits;
        #pragma unroll
        for (int it = 0; it < 4; it++) {
            int q = t + it * 512;               // 0..2047
            int ii = q >> 10;
            int h = (q >> 7) & 7;
            int cc = q & 127;
            scv[q] = gl[((size_t)((b * 8 + h) * 512) + i0 + ii) * 128 + cc];
        }
    }
    __syncthreads();

    { // softmax: warp w handles row (ii = w>>3, h = w&7)
        float* row = sc[w >> 3][w & 7];
        float x[16];
        #pragma unroll
        for (int k = 0; k < 16; k++) x[k] = row[lane + k * 32];
        float m = x[0];
        #pragma unroll
        for (int k = 1; k < 16; k++) m = fmaxf(m, x[k]);
        #pragma unroll
        for (int off = 16; off > 0; off >>= 1)
            m = fmaxf(m, __shfl_xor_sync(0xffffffffu, m, off));
        float e[16], s = 0.f;
        #pragma unroll
        for (int k = 0; k < 16; k++) { e[k] = __expf(x[k] - m); s += e[k]; }
        #pragma unroll
        for (int off = 16; off > 0; off >>= 1)
            s += __shfl_xor_sync(0xffffffffu, s, off);
        float inv = 1.0f / s;
        #pragma unroll
        for (int k = 0; k < 16; k++) row[lane + k * 32] = e[k] * inv;
    }
    __syncthreads();

    {
        int o = t & 127;
        int jq = t >> 7;                        // 0..3 j-quarter
        int h = o >> 4;
        const float* vb = g_val + (size_t)b * 65536 + (size_t)(jq * 128) * 128 + o;
        const float* cf0 = &sc[0][h][jq * 128];
        const float* cf1 = &sc[1][h][jq * 128];
        float a0 = 0.f, a1 = 0.f;
        #pragma unroll 8
        for (int j = 0; j < 128; j++) {
            float v = vb[(size_t)j * 128];
            a0 = fmaf(cf0[j], v, a0);
            a1 = fmaf(cf1[j], v, a1);
        }
        sacc[jq][0][o] = a0;
        sacc[jq][1][o] = a1;
    }
    __syncthreads();

    int o2 = t & 127;
    int i2 = (t >> 7) & 1;
    bool active = t < 256;
    float r = 0.f;
    size_t base = ((size_t)(b * 512) + i0 + i2) * 128 + o2;
    if (active) {
        r = sacc[0][i2][o2] + sacc[1][i2][o2] + sacc[2][i2][o2] + sacc[3][i2][o2]
          + g_skip[base];
        r = fmaxf(r, 0.f);
        float s1 = r, s2 = r * r;
        #pragma unroll
        for (int off = 16; off > 0; off >>= 1) {
            s1 += __shfl_xor_sync(0xffffffffu, s1, off);
            s2 += __shfl_xor_sync(0xffffffffu, s2, off);
        }
        if (lane == 0) {
            int wq = (t >> 5) & 3;
            red[i2][wq][0] = s1;
            red[i2][wq][1] = s2;
        }
    }
    __syncthreads();
    if (active) {
        float s1 = red[i2][0][0] + red[i2][1][0] + red[i2][2][0] + red[i2][3][0];
        float s2 = red[i2][0][1] + red[i2][1][1] + red[i2][2][1] + red[i2][3][1];
        float mean = s1 * (1.0f / 128.0f);
        float var = s2 * (1.0f / 128.0f) - mean * mean;
        out[base] = (r - mean) * rsqrtf(var + 1e-5f) * ln_scale[o2] + ln_offset[o2];
    }
}

// ---------------- launch ----------------
extern "C" void kernel_launch(void* const* d_in, const int* in_sizes, int n_in,
                              void* d_out, int out_size) {
    const float* node   = (const float*)d_in[0];
    const float* edge   = (const float*)d_in[1];
    const float* graph  = (const float*)d_in[2];
    const float* adj    = (const float*)d_in[3];
    const float* m_w    = (const float*)d_in[5];
    const float* m_b    = (const float*)d_in[6];
    const float* skip_w = (const float*)d_in[7];
    const float* skip_b = (const float*)d_in[8];
    const float* w1_w   = (const float*)d_in[9];
    const float* w1_b   = (const float*)d_in[10];
    const float* w2_w   = (const float*)d_in[11];
    const float* w2_b   = (const float*)d_in[12];
    const float* we_w   = (const float*)d_in[13];
    const float* we_b   = (const float*)d_in[14];
    const float* wg_w   = (const float*)d_in[15];
    const float* wg_b   = (const float*)d_in[16];
    const float* a_w    = (const float*)d_in[17];
    const float* a_b    = (const float*)d_in[18];
    const float* ln_s   = (const float*)d_in[19];
    const float* ln_o   = (const float*)d_in[20];
    float* out = (float*)d_out;

    // sW 34816 + sE 17408 + sP 17408 + (128+128+8)*4 = 70688 dynamic
    const int EDGE_SMEM = 70688;
    cudaFuncSetAttribute(edge_k, cudaFuncAttributeMaxDynamicSharedMemorySize, EDGE_SMEM);

    fill_k<<<2048, 256>>>();
    prep_k<<<8, 128>>>(graph, wg_w, wg_b, we_w);
    node_k<<<256, 128>>>(node, m_w, m_b, skip_w, skip_b, w1_w, w1_b, w2_w, w2_b, we_b);
    edge_k<<<2048, 256, EDGE_SMEM>>>(edge, adj, a_w, a_b);
    out_k<<<1024, 512>>>(ln_s, ln_o, out);
}